// round 15
// baseline (speedup 1.0000x reference)
#include <cuda_runtime.h>
#include <cstdint>

// HighOrderActivation: B=1024, G=512, K=4, D=64.
// out[b,g,:] = c0*P[g,15,:] + c1*P[g,id1,:] + c2*P[g,id2,:] + c3*P[g,id3,:]
// (i0..i3)=argsort(X[b,g,:]); c=(min, gaps); id1=15-2^i0, id2=2^i2+2^i3, id3=2^i3.
//
// R13: R3 layout (one pair/thread, 8 lanes/pair, one g per block, warp = 4
// consecutive b) with 256-BIT global accesses (sm_100+ ld/st.global.v8.f32).
// The binder is LSU instruction-slot cost (STG.128=12cyc, LDG floor 4):
// R3 spent ~60 cyc/warp on 11 mem instrs. v8 halves the instruction count:
// 4 gather LDG.256 + 1 X LDG.128 + 1 STG.256 ≈ 38 cyc/warp. Bytes unchanged,
// precision unchanged (fp32).

#define BATCH   1024
#define GROUPS  512
#define B_TILE  32
#define PAIRS   (BATCH * GROUPS)

__device__ __forceinline__ void ldg256(const float* __restrict__ p, float r[8])
{
    asm volatile("ld.global.nc.v8.f32 {%0,%1,%2,%3,%4,%5,%6,%7}, [%8];"
                 : "=f"(r[0]), "=f"(r[1]), "=f"(r[2]), "=f"(r[3]),
                   "=f"(r[4]), "=f"(r[5]), "=f"(r[6]), "=f"(r[7])
                 : "l"(p));
}

__device__ __forceinline__ void stg256(float* __restrict__ p, const float r[8])
{
    asm volatile("st.global.v8.f32 [%0], {%1,%2,%3,%4,%5,%6,%7,%8};"
                 :: "l"(p),
                    "f"(r[0]), "f"(r[1]), "f"(r[2]), "f"(r[3]),
                    "f"(r[4]), "f"(r[5]), "f"(r[6]), "f"(r[7])
                 : "memory");
}

__global__ __launch_bounds__(256, 6)
void hoa_kernel(const float4* __restrict__ Xv,      // [PAIRS] float4
                const float*  __restrict__ Pf,      // [GROUPS*16*64] f32
                float*        __restrict__ Of)      // [PAIRS*64] f32
{
    const int tid = threadIdx.x;
    const int g   = blockIdx.x & (GROUPS - 1);      // block-uniform group
    const int b   = ((blockIdx.x >> 9) << 5) + (tid >> 3);
    const int q8  = (tid & 7) * 8;                  // float offset 0..56

    const int p = b * GROUPS + g;

    // One 16B broadcast load per pair (8 lanes share the line).
    const float4 x = Xv[p];

    float v0 = x.x, v1 = x.y, v2 = x.z, v3 = x.w;
    int   i0 = 0,   i1 = 1,   i2 = 2,   i3 = 3;

    // 5-comparator sorting network, FMNMX + SEL.
    {
        bool sw; float lo, hi; int t;
        sw = v0 > v1; lo = fminf(v0, v1); hi = fmaxf(v0, v1); v0 = lo; v1 = hi;
        t = i0; i0 = sw ? i1 : i0; i1 = sw ? t : i1;
        sw = v2 > v3; lo = fminf(v2, v3); hi = fmaxf(v2, v3); v2 = lo; v3 = hi;
        t = i2; i2 = sw ? i3 : i2; i3 = sw ? t : i3;
        sw = v0 > v2; lo = fminf(v0, v2); hi = fmaxf(v0, v2); v0 = lo; v2 = hi;
        t = i0; i0 = sw ? i2 : i0; i2 = sw ? t : i2;
        sw = v1 > v3; lo = fminf(v1, v3); hi = fmaxf(v1, v3); v1 = lo; v3 = hi;
        t = i1; i1 = sw ? i3 : i1; i3 = sw ? t : i3;
        sw = v1 > v2; lo = fminf(v1, v2); hi = fmaxf(v1, v2); v1 = lo; v2 = hi;
        t = i1; i1 = sw ? i2 : i1; i2 = sw ? t : i2;
    }

    const float c0 = v0;
    const float c1 = v1 - v0;
    const float c2 = v2 - v1;
    const float c3 = v3 - v2;

    const int e0 = 1 << i0;
    const int e2 = 1 << i2;
    const int e3 = 1 << i3;
    const int id1 = 15 - e0;
    const int id2 = e2 + e3;
    const int id3 = e3;

    // params[g]: [16 rows, 64 f32]; each lane owns a 32B slice of the row.
    const float* __restrict__ base = Pf + g * 1024 + q8;

    float r0[8], r1[8], r2[8], r3[8];
    ldg256(base + 15  * 64, r0);
    ldg256(base + id1 * 64, r1);
    ldg256(base + id2 * 64, r2);
    ldg256(base + id3 * 64, r3);

    float acc[8];
    #pragma unroll
    for (int j = 0; j < 8; ++j) {
        acc[j] = c0 * r0[j] + c1 * r1[j] + c2 * r2[j] + c3 * r3[j];
    }

    stg256(Of + (size_t)p * 64 + q8, acc);
}

extern "C" void kernel_launch(void* const* d_in, const int* in_sizes, int n_in,
                              void* d_out, int out_size)
{
    const float4* Xv = (const float4*)d_in[0];   // X: [1024, 512, 4] f32
    const float*  Pf = (const float*)d_in[1];    // params: [512, 16, 64] f32
    float*        Of = (float*)d_out;            // out: [1024, 512, 64] f32

    // One block per (g, 32-b tile): 512 * 32 = 16384 blocks, 256 threads.
    const int grid = GROUPS * (BATCH / B_TILE);
    hoa_kernel<<<grid, 256>>>(Xv, Pf, Of);
}

// round 16
// speedup vs baseline: 1.0766x; 1.0766x over previous
#include <cuda_runtime.h>
#include <cstdint>

// HighOrderActivation: B=1024, G=512, K=4, D=64.
// out[b,g,:] = c0*P[g,15,:] + c1*P[g,id1,:] + c2*P[g,id2,:] + c3*P[g,id3,:]
// (i0..i3)=argsort(X[b,g,:]); c=(min, gaps); id1=15-2^i0, id2=2^i2+2^i3, id3=2^i3.
//
// R15: stores moved off the LSU issue path. R3's budget was 60 cyc/warp with
// 24 cyc (40%) in 2x STG.128 (12cyc each, 2.3x byte cost). Now: results are
// staged in smem via STS.128 (byte-cost, 4cyc) and each CTA emits ONE 8KB
// descriptor-free cp.async.bulk TMA store. Contiguity requires CTA = (one b,
// 32 consecutive g) -> out[b, g0..g0+31, :] is one contiguous 8KB block.
// Gathers (already at byte floor) and X structure unchanged; params L2-hot.

#define BATCH   1024
#define GROUPS  512
#define G_TILE  32          // g-values per CTA (256 threads, 8 lanes/pair)

__global__ __launch_bounds__(256, 8)
void hoa_kernel(const float4* __restrict__ Xv,      // [B*G] float4
                const float4* __restrict__ Pv,      // [G*256] float4
                float*        __restrict__ Of)      // [B*G*64] f32
{
    __shared__ float4 sOut[G_TILE * 16];            // 32 pairs x 256B = 8KB

    const int tid = threadIdx.x;
    const int b   = blockIdx.x >> 4;                // batch index
    const int gt  = blockIdx.x & 15;                // g-tile (0..15)
    const int pr  = tid >> 3;                       // pair-in-CTA (0..31)
    const int q   = tid & 7;                        // float4 chunk 0..7

    const int g = gt * G_TILE + pr;
    const int p = b * GROUPS + g;

    // X[b, g0..g0+3, :] contiguous for the warp's 4 pairs: one 64B line.
    const float4 x = Xv[p];

    float v0 = x.x, v1 = x.y, v2 = x.z, v3 = x.w;
    int   i0 = 0,   i1 = 1,   i2 = 2,   i3 = 3;

    // 5-comparator sorting network, FMNMX + SEL.
    {
        bool sw; float lo, hi; int t;
        sw = v0 > v1; lo = fminf(v0, v1); hi = fmaxf(v0, v1); v0 = lo; v1 = hi;
        t = i0; i0 = sw ? i1 : i0; i1 = sw ? t : i1;
        sw = v2 > v3; lo = fminf(v2, v3); hi = fmaxf(v2, v3); v2 = lo; v3 = hi;
        t = i2; i2 = sw ? i3 : i2; i3 = sw ? t : i3;
        sw = v0 > v2; lo = fminf(v0, v2); hi = fmaxf(v0, v2); v0 = lo; v2 = hi;
        t = i0; i0 = sw ? i2 : i0; i2 = sw ? t : i2;
        sw = v1 > v3; lo = fminf(v1, v3); hi = fmaxf(v1, v3); v1 = lo; v3 = hi;
        t = i1; i1 = sw ? i3 : i1; i3 = sw ? t : i3;
        sw = v1 > v2; lo = fminf(v1, v2); hi = fmaxf(v1, v2); v1 = lo; v2 = hi;
        t = i1; i1 = sw ? i2 : i1; i2 = sw ? t : i2;
    }

    const float c0 = v0;
    const float c1 = v1 - v0;
    const float c2 = v2 - v1;
    const float c3 = v3 - v2;

    const int e0 = 1 << i0;
    const int e2 = 1 << i2;
    const int e3 = 1 << i3;
    const int id1 = 15 - e0;
    const int id2 = e2 + e3;
    const int id3 = e3;

    // params[g]: [16 rows, 16 float4]; per-pair table (L2-resident, 2MB total).
    const float4* __restrict__ base = Pv + g * 256;

    const float4* r0 = base + 15  * 16 + q;
    const float4* r1 = base + id1 * 16 + q;
    const float4* r2 = base + id2 * 16 + q;
    const float4* r3 = base + id3 * 16 + q;

    const float4 a0 = r0[0], bb0 = r0[8];
    const float4 a1 = r1[0], bb1 = r1[8];
    const float4 a2 = r2[0], bb2 = r2[8];
    const float4 a3 = r3[0], bb3 = r3[8];

    float4 oa, ob;
    oa.x = c0 * a0.x + c1 * a1.x + c2 * a2.x + c3 * a3.x;
    oa.y = c0 * a0.y + c1 * a1.y + c2 * a2.y + c3 * a3.y;
    oa.z = c0 * a0.z + c1 * a1.z + c2 * a2.z + c3 * a3.z;
    oa.w = c0 * a0.w + c1 * a1.w + c2 * a2.w + c3 * a3.w;

    ob.x = c0 * bb0.x + c1 * bb1.x + c2 * bb2.x + c3 * bb3.x;
    ob.y = c0 * bb0.y + c1 * bb1.y + c2 * bb2.y + c3 * bb3.y;
    ob.z = c0 * bb0.z + c1 * bb1.z + c2 * bb2.z + c3 * bb3.z;
    ob.w = c0 * bb0.w + c1 * bb1.w + c2 * bb2.w + c3 * bb3.w;

    // Stage to smem (byte-cost stores), layout == gmem layout of the block.
    sOut[pr * 16 + q]     = oa;
    sOut[pr * 16 + q + 8] = ob;

    __syncthreads();

    // One 8KB descriptor-free bulk TMA store: smem -> out[b, g0.., :].
    if (tid == 0) {
        uint32_t saddr;
        asm("{ .reg .u64 t; cvta.to.shared.u64 t, %1; cvt.u32.u64 %0, t; }"
            : "=r"(saddr) : "l"(sOut));
        float* gdst = Of + ((size_t)b * GROUPS + (size_t)gt * G_TILE) * 64;
        asm volatile("fence.proxy.async.shared::cta;" ::: "memory");
        asm volatile("cp.async.bulk.global.shared::cta.bulk_group [%0], [%1], %2;"
                     :: "l"(gdst), "r"(saddr), "r"(G_TILE * 16 * 16)
                     : "memory");
        asm volatile("cp.async.bulk.commit_group;" ::: "memory");
        asm volatile("cp.async.bulk.wait_group 0;" ::: "memory");
    }
}

extern "C" void kernel_launch(void* const* d_in, const int* in_sizes, int n_in,
                              void* d_out, int out_size)
{
    const float4* Xv = (const float4*)d_in[0];   // X: [1024, 512, 4] f32
    const float4* Pv = (const float4*)d_in[1];   // params: [512, 16, 64] f32
    float*        Of = (float*)d_out;            // out: [1024, 512, 64] f32

    // One block per (b, 32-g tile): 1024 * 16 = 16384 blocks, 256 threads.
    const int grid = BATCH * (GROUPS / G_TILE);
    hoa_kernel<<<grid, 256>>>(Xv, Pv, Of);
}

// round 17
// speedup vs baseline: 1.1077x; 1.0289x over previous
#include <cuda_runtime.h>
#include <cstdint>

// HighOrderActivation: B=1024, G=512, K=4, D=64.
// out[b,g,:] = c0*P[g,15,:] + c1*P[g,id1,:] + c2*P[g,id2,:] + c3*P[g,id3,:]
// (i0..i3)=argsort(X[b,g,:]); c=(min, gaps); id1=15-2^i0, id2=2^i2+2^i3, id3=2^i3.
//
// R16 = R3 gather locality + R15 store path, combined.
//  - CTA = one g, 32 consecutive b (4KB params table stays L1-resident;
//    R15's mistake was 128KB/CTA -> L2 round-trips).
//  - Results staged in smem (STS.128 at byte cost) and written by ONE 256B
//    cp.async.bulk per pair (lane q==0), replacing 2x STG.128 (12cyc each,
//    40% of R3's LSU budget). 256B = 2 full lines per row.
//  - No __syncthreads: each pair's smem region is warp-synchronous
//    (__syncwarp + fence.proxy.async before the bulk issue).

#define BATCH   1024
#define GROUPS  512
#define B_TILE  32

__global__ __launch_bounds__(256, 8)
void hoa_kernel(const float4* __restrict__ Xv,      // [B*G] float4
                const float4* __restrict__ Pv,      // [G*256] float4
                float*        __restrict__ Of)      // [B*G*64] f32
{
    __shared__ float4 sOut[B_TILE * 16];            // 32 pairs x 256B = 8KB

    const int tid = threadIdx.x;
    const int g   = blockIdx.x & (GROUPS - 1);      // block-uniform group
    const int pr  = tid >> 3;                       // pair-in-CTA (0..31)
    const int q   = tid & 7;                        // float4 chunk 0..7
    const int b   = ((blockIdx.x >> 9) << 5) + pr;

    const int p = b * GROUPS + g;

    // One 16B broadcast load per pair (8 lanes share the line).
    const float4 x = Xv[p];

    float v0 = x.x, v1 = x.y, v2 = x.z, v3 = x.w;
    int   i0 = 0,   i1 = 1,   i2 = 2,   i3 = 3;

    // 5-comparator sorting network, FMNMX + SEL.
    {
        bool sw; float lo, hi; int t;
        sw = v0 > v1; lo = fminf(v0, v1); hi = fmaxf(v0, v1); v0 = lo; v1 = hi;
        t = i0; i0 = sw ? i1 : i0; i1 = sw ? t : i1;
        sw = v2 > v3; lo = fminf(v2, v3); hi = fmaxf(v2, v3); v2 = lo; v3 = hi;
        t = i2; i2 = sw ? i3 : i2; i3 = sw ? t : i3;
        sw = v0 > v2; lo = fminf(v0, v2); hi = fmaxf(v0, v2); v0 = lo; v2 = hi;
        t = i0; i0 = sw ? i2 : i0; i2 = sw ? t : i2;
        sw = v1 > v3; lo = fminf(v1, v3); hi = fmaxf(v1, v3); v1 = lo; v3 = hi;
        t = i1; i1 = sw ? i3 : i1; i3 = sw ? t : i3;
        sw = v1 > v2; lo = fminf(v1, v2); hi = fmaxf(v1, v2); v1 = lo; v2 = hi;
        t = i1; i1 = sw ? i2 : i1; i2 = sw ? t : i2;
    }

    const float c0 = v0;
    const float c1 = v1 - v0;
    const float c2 = v2 - v1;
    const float c3 = v3 - v2;

    const int e0 = 1 << i0;
    const int e2 = 1 << i2;
    const int e3 = 1 << i3;
    const int id1 = 15 - e0;
    const int id2 = e2 + e3;
    const int id3 = e3;

    // params[g]: [16 rows, 16 float4]; block-uniform, L1-resident (4KB).
    const float4* __restrict__ base = Pv + g * 256;

    const float4* r0 = base + 15  * 16 + q;
    const float4* r1 = base + id1 * 16 + q;
    const float4* r2 = base + id2 * 16 + q;
    const float4* r3 = base + id3 * 16 + q;

    const float4 a0 = r0[0], bb0 = r0[8];
    const float4 a1 = r1[0], bb1 = r1[8];
    const float4 a2 = r2[0], bb2 = r2[8];
    const float4 a3 = r3[0], bb3 = r3[8];

    float4 oa, ob;
    oa.x = c0 * a0.x + c1 * a1.x + c2 * a2.x + c3 * a3.x;
    oa.y = c0 * a0.y + c1 * a1.y + c2 * a2.y + c3 * a3.y;
    oa.z = c0 * a0.z + c1 * a1.z + c2 * a2.z + c3 * a3.z;
    oa.w = c0 * a0.w + c1 * a1.w + c2 * a2.w + c3 * a3.w;

    ob.x = c0 * bb0.x + c1 * bb1.x + c2 * bb2.x + c3 * bb3.x;
    ob.y = c0 * bb0.y + c1 * bb1.y + c2 * bb2.y + c3 * bb3.y;
    ob.z = c0 * bb0.z + c1 * bb1.z + c2 * bb2.z + c3 * bb3.z;
    ob.w = c0 * bb0.w + c1 * bb1.w + c2 * bb2.w + c3 * bb3.w;

    // Stage this pair's 256B row in smem (byte-cost stores).
    sOut[pr * 16 + q]     = oa;
    sOut[pr * 16 + q + 8] = ob;

    __syncwarp();

    // Lane 0 of each 8-lane pair issues ONE 256B bulk store smem -> gmem.
    if (q == 0) {
        uint32_t saddr;
        asm("{ .reg .u64 t; cvta.to.shared.u64 t, %1; cvt.u32.u64 %0, t; }"
            : "=r"(saddr) : "l"(&sOut[pr * 16]));
        float* gdst = Of + (size_t)p * 64;
        asm volatile("fence.proxy.async.shared::cta;" ::: "memory");
        asm volatile("cp.async.bulk.global.shared::cta.bulk_group [%0], [%1], 256;"
                     :: "l"(gdst), "r"(saddr)
                     : "memory");
        asm volatile("cp.async.bulk.commit_group;" ::: "memory");
        asm volatile("cp.async.bulk.wait_group 0;" ::: "memory");
    }
}

extern "C" void kernel_launch(void* const* d_in, const int* in_sizes, int n_in,
                              void* d_out, int out_size)
{
    const float4* Xv = (const float4*)d_in[0];   // X: [1024, 512, 4] f32
    const float4* Pv = (const float4*)d_in[1];   // params: [512, 16, 64] f32
    float*        Of = (float*)d_out;            // out: [1024, 512, 64] f32

    // One block per (g, 32-b tile): 512 * 32 = 16384 blocks, 256 threads.
    const int grid = GROUPS * (BATCH / B_TILE);
    hoa_kernel<<<grid, 256>>>(Xv, Pv, Of);
}